// round 1
// baseline (speedup 1.0000x reference)
#include <cuda_runtime.h>

#define TPB 256

__global__ __launch_bounds__(TPB, 1)
void seal_kernel(
    const int* __restrict__ labels,
    const int* __restrict__ src,
    const int* __restrict__ dst,
    const float* __restrict__ emb,
    const float* __restrict__ w1_0, const float* __restrict__ b1_0,
    const float* __restrict__ w2_0, const float* __restrict__ b2_0,
    const float* __restrict__ w1_1, const float* __restrict__ b1_1,
    const float* __restrict__ w2_1, const float* __restrict__ b2_1,
    const float* __restrict__ w1_2, const float* __restrict__ b1_2,
    const float* __restrict__ w2_2, const float* __restrict__ b2_2,
    const float* __restrict__ conv1_w, const float* __restrict__ conv1_b,
    const float* __restrict__ conv2_w, const float* __restrict__ conv2_b,
    const float* __restrict__ sc_w1, const float* __restrict__ sc_b1,
    const float* __restrict__ sc_w2, const float* __restrict__ sc_b2,
    float* __restrict__ out)
{
    // pool is a union region:
    //   GIN phase : bufA[64*33] | bufB[64*33] | wbuf[2112]  (w1 @0, b1 @1024, w2 @1056, b2 @2080)
    //   conv1     : weights stride-165 per out-channel (32*165=5280) + bias @5280
    //   conv2     : weights stride-165 (16*165=2640) + bias @2640 + scorer params @2660..2960
    __shared__ float pool[6336];
    __shared__ int   starts[65];
    __shared__ int   cursor[64];
    __shared__ unsigned short esrc[1024];
    __shared__ float pooled[10 * 33];
    __shared__ float ybuf[32 * 5];
    __shared__ float c2buf[16 * 5];
    __shared__ float feat[16];
    __shared__ float hidbuf[16];
    __shared__ int   nodeOfRank[10];

    float* bufA = pool;
    float* bufB = pool + 64 * 33;
    float* wbuf = pool + 64 * 66;

    const int g = blockIdx.x;
    const int t = threadIdx.x;

    // ------------------------------------------------------------------
    // Build per-graph CSR keyed by destination (topology reused 3x)
    // ------------------------------------------------------------------
    if (t < 64) cursor[t] = 0;
    __syncthreads();

    int es[4], ed[4];
    const int* gsrc = src + g * 1024;
    const int* gdst = dst + g * 1024;
    #pragma unroll
    for (int i = 0; i < 4; i++) {
        const int e = t + i * TPB;
        es[i] = gsrc[e] & 63;          // local node id (block-aligned graphs)
        ed[i] = gdst[e] & 63;
        atomicAdd(&cursor[ed[i]], 1);
    }
    __syncthreads();
    if (t == 0) {
        int acc = 0;
        for (int i = 0; i < 64; i++) { starts[i] = acc; acc += cursor[i]; }
        starts[64] = acc;
    }
    __syncthreads();
    if (t < 64) cursor[t] = starts[t];
    __syncthreads();
    #pragma unroll
    for (int i = 0; i < 4; i++) {
        const int pos = atomicAdd(&cursor[ed[i]], 1);
        esrc[pos] = (unsigned short)es[i];
    }

    // ------------------------------------------------------------------
    // DRNL embedding lookup -> bufA (64 x 16)
    // ------------------------------------------------------------------
    const int* glab = labels + g * 64;
    for (int idx = t; idx < 64 * 16; idx += TPB) {
        const int n = idx >> 4, c = idx & 15;
        bufA[n * 33 + c] = emb[glab[n] * 16 + c];
    }
    __syncthreads();

    const float* W1s[3] = { w1_0, w1_1, w1_2 };
    const float* B1s[3] = { b1_0, b1_1, b1_2 };
    const float* W2s[3] = { w2_0, w2_1, w2_2 };
    const float* B2s[3] = { b2_0, b2_1, b2_2 };

    float* cur = bufA;
    float* oth = bufB;

    // ------------------------------------------------------------------
    // 3 GIN layers: h = relu(relu((h + agg) @ W1 + b1) @ W2 + b2)
    // ------------------------------------------------------------------
    #pragma unroll
    for (int l = 0; l < 3; l++) {
        const int din = (l == 0) ? 16 : 32;

        // stage this layer's weights in SMEM
        for (int idx = t; idx < din * 32; idx += TPB) wbuf[idx] = W1s[l][idx];
        if (t < 32)             wbuf[1024 + t]        = B1s[l][t];
        for (int idx = t; idx < 1024; idx += TPB)   wbuf[1056 + idx] = W2s[l][idx];
        if (t >= 32 && t < 64)  wbuf[2080 + (t - 32)] = B2s[l][t - 32];
        __syncthreads();

        // ---- z = h + sum_{incoming} h[src] ----
        {
            const int n   = t >> 2;
            const int cpt = din >> 2;            // 4 or 8 channels per thread
            const int c0  = (t & 3) * cpt;
            float acc[8];
            #pragma unroll
            for (int j = 0; j < 8; j++) if (j < cpt) acc[j] = cur[n * 33 + c0 + j];
            const int e0 = starts[n], e1 = starts[n + 1];
            for (int e = e0; e < e1; e++) {
                const int s = esrc[e];
                #pragma unroll
                for (int j = 0; j < 8; j++) if (j < cpt) acc[j] += cur[s * 33 + c0 + j];
            }
            #pragma unroll
            for (int j = 0; j < 8; j++) if (j < cpt) oth[n * 33 + c0 + j] = acc[j];
        }
        __syncthreads();
        { float* tmp = cur; cur = oth; oth = tmp; }

        // ---- t1 = relu(z @ W1 + b1)  (din -> 32) ----
        {
            const int n  = t >> 2;
            const int o0 = (t & 3) * 8;
            float acc[8];
            #pragma unroll
            for (int j = 0; j < 8; j++) acc[j] = wbuf[1024 + o0 + j];
            for (int k = 0; k < din; k++) {
                const float v = cur[n * 33 + k];
                #pragma unroll
                for (int j = 0; j < 8; j++) acc[j] += v * wbuf[k * 32 + o0 + j];
            }
            #pragma unroll
            for (int j = 0; j < 8; j++) oth[n * 33 + o0 + j] = fmaxf(acc[j], 0.f);
        }
        __syncthreads();
        { float* tmp = cur; cur = oth; oth = tmp; }

        // ---- h' = relu(t1 @ W2 + b2)  (32 -> 32) ----
        {
            const int n  = t >> 2;
            const int o0 = (t & 3) * 8;
            float acc[8];
            #pragma unroll
            for (int j = 0; j < 8; j++) acc[j] = wbuf[2080 + o0 + j];
            #pragma unroll
            for (int k = 0; k < 32; k++) {
                const float v = cur[n * 33 + k];
                #pragma unroll
                for (int j = 0; j < 8; j++) acc[j] += v * wbuf[1056 + k * 32 + o0 + j];
            }
            #pragma unroll
            for (int j = 0; j < 8; j++) oth[n * 33 + o0 + j] = fmaxf(acc[j], 0.f);
        }
        __syncthreads();
        { float* tmp = cur; cur = oth; oth = tmp; }
    }

    // ------------------------------------------------------------------
    // SortPooling: rank nodes by channel 31 descending (stable), keep 10
    // ------------------------------------------------------------------
    if (t < 64) {
        const float key = cur[t * 33 + 31];
        int r = 0;
        for (int m = 0; m < 64; m++) {
            const float km = cur[m * 33 + 31];
            r += (km > key) || (km == key && m < t);
        }
        if (r < 10) nodeOfRank[r] = t;
    }
    __syncthreads();
    for (int idx = t; idx < 10 * 32; idx += TPB) {
        const int k = idx >> 5, c = idx & 31;
        pooled[k * 33 + c] = cur[nodeOfRank[k] * 33 + c];
    }
    __syncthreads();

    // ------------------------------------------------------------------
    // Conv1 (32->32, k=5, pad=2) + ReLU fused with MaxPool1d(2,2)
    // weights restaged stride-165 (5*co+x mod 32 -> conflict-free)
    // ------------------------------------------------------------------
    for (int idx = t; idx < 32 * 160; idx += TPB) {
        const int co = idx / 160, r = idx - co * 160;
        pool[co * 165 + r] = conv1_w[idx];
    }
    if (t < 32) pool[5280 + t] = conv1_b[t];
    __syncthreads();

    if (t < 160) {
        const int co = t & 31, q = t >> 5;     // q = pooled output position 0..4
        float a0 = pool[5280 + co];
        float a1 = a0;
        const float* wrow = pool + co * 165;
        for (int ci = 0; ci < 32; ci++) {
            #pragma unroll
            for (int k = 0; k < 5; k++) {
                const float w = wrow[ci * 5 + k];
                const int p0 = 2 * q + k - 2;
                const int p1 = p0 + 1;
                if (p0 >= 0 && p0 < 10) a0 += w * pooled[p0 * 33 + ci];
                if (p1 >= 0 && p1 < 10) a1 += w * pooled[p1 * 33 + ci];
            }
        }
        ybuf[co * 5 + q] = fmaxf(fmaxf(a0, 0.f), fmaxf(a1, 0.f));
    }
    __syncthreads();

    // ------------------------------------------------------------------
    // Conv2 (32->16, k=5, pad=2) + ReLU, then mean + scorer MLP
    // ------------------------------------------------------------------
    for (int idx = t; idx < 16 * 160; idx += TPB) {
        const int co = idx / 160, r = idx - co * 160;
        pool[co * 165 + r] = conv2_w[idx];
    }
    if (t < 16)                pool[2640 + t]        = conv2_b[t];
    for (int idx = t; idx < 256; idx += TPB) pool[2660 + idx] = sc_w1[idx];
    if (t < 16)                pool[2920 + t]        = sc_b1[t];
    if (t >= 16 && t < 32)     pool[2940 + (t - 16)] = sc_w2[t - 16];
    if (t == 32)               pool[2960]            = sc_b2[0];
    __syncthreads();

    if (t < 80) {
        const int co = t & 15, p = t >> 4;     // p = 0..4
        float a = pool[2640 + co];
        const float* wrow = pool + co * 165;
        for (int ci = 0; ci < 32; ci++) {
            #pragma unroll
            for (int k = 0; k < 5; k++) {
                const int q = p + k - 2;
                if (q >= 0 && q < 5) a += wrow[ci * 5 + k] * ybuf[ci * 5 + q];
            }
        }
        c2buf[co * 5 + p] = fmaxf(a, 0.f);
    }
    __syncthreads();

    if (t < 16) {
        feat[t] = 0.2f * (c2buf[t * 5 + 0] + c2buf[t * 5 + 1] + c2buf[t * 5 + 2] +
                          c2buf[t * 5 + 3] + c2buf[t * 5 + 4]);
    }
    __syncthreads();

    if (t < 16) {
        float a = pool[2920 + t];
        #pragma unroll
        for (int i = 0; i < 16; i++) a += feat[i] * pool[2660 + i * 16 + t];
        hidbuf[t] = fmaxf(a, 0.f);
    }
    __syncthreads();

    if (t == 0) {
        float s = pool[2960];
        #pragma unroll
        for (int j = 0; j < 16; j++) s += hidbuf[j] * pool[2940 + j];
        out[g] = s;
    }
}

extern "C" void kernel_launch(void* const* d_in, const int* in_sizes, int n_in,
                              void* d_out, int out_size)
{
    const int B = in_sizes[0] / 64;   // nodes per graph = 64
    seal_kernel<<<B, TPB>>>(
        (const int*)d_in[0], (const int*)d_in[1], (const int*)d_in[2],
        (const float*)d_in[3],
        (const float*)d_in[4],  (const float*)d_in[5],
        (const float*)d_in[6],  (const float*)d_in[7],
        (const float*)d_in[8],  (const float*)d_in[9],
        (const float*)d_in[10], (const float*)d_in[11],
        (const float*)d_in[12], (const float*)d_in[13],
        (const float*)d_in[14], (const float*)d_in[15],
        (const float*)d_in[16], (const float*)d_in[17],
        (const float*)d_in[18], (const float*)d_in[19],
        (const float*)d_in[20], (const float*)d_in[21],
        (const float*)d_in[22], (const float*)d_in[23],
        (float*)d_out);
}

// round 2
// speedup vs baseline: 1.3772x; 1.3772x over previous
#include <cuda_runtime.h>

typedef unsigned long long u64;

__device__ __forceinline__ u64 pack2(float x, float y) {
    u64 r; asm("mov.b64 %0, {%1, %2};" : "=l"(r) : "f"(x), "f"(y)); return r;
}
__device__ __forceinline__ void unpack2(u64 v, float& x, float& y) {
    asm("mov.b64 {%0, %1}, %2;" : "=f"(x), "=f"(y) : "l"(v));
}
__device__ __forceinline__ u64 ffma2(u64 a, u64 b, u64 c) {
    u64 d; asm("fma.rn.f32x2 %0, %1, %2, %3;" : "=l"(d) : "l"(a), "l"(b), "l"(c));
    return d;
}

// GEMM: zout[n, o] = relu(bias[o] + sum_k zin[n,k] * W[k,o]); 64 nodes, 32 outs.
// Thread layout (t < 128): node pair = t>>2, out group o0 = (t&3)*8.
__device__ __forceinline__ void gemm_relu(const float* __restrict__ zin,
                                          float* __restrict__ zout,
                                          const float* __restrict__ W,
                                          const float* __restrict__ bias,
                                          int din, int t)
{
    if (t < 128) {
        const int n0 = (t >> 2) * 2;
        const int n1 = n0 + 1;
        const int o0 = (t & 3) * 8;
        const float* wb = W + o0;
        u64 aA[4], aB[4];
        {
            const float4 b0 = *(const float4*)(bias + o0);
            const float4 b1 = *(const float4*)(bias + o0 + 4);
            aA[0] = pack2(b0.x, b0.y); aA[1] = pack2(b0.z, b0.w);
            aA[2] = pack2(b1.x, b1.y); aA[3] = pack2(b1.z, b1.w);
            aB[0] = aA[0]; aB[1] = aA[1]; aB[2] = aA[2]; aB[3] = aA[3];
        }
        const float* zA = zin + n0 * 34;
        const float* zB = zin + n1 * 34;
        for (int k = 0; k < din; k += 2) {
            const float2 vA = *(const float2*)(zA + k);
            const float2 vB = *(const float2*)(zB + k);
            const float4 w00 = *(const float4*)(wb + k * 32);
            const float4 w01 = *(const float4*)(wb + k * 32 + 4);
            const float4 w10 = *(const float4*)(wb + (k + 1) * 32);
            const float4 w11 = *(const float4*)(wb + (k + 1) * 32 + 4);
            const u64 p00 = pack2(w00.x, w00.y), p01 = pack2(w00.z, w00.w);
            const u64 p02 = pack2(w01.x, w01.y), p03 = pack2(w01.z, w01.w);
            const u64 p10 = pack2(w10.x, w10.y), p11 = pack2(w10.z, w10.w);
            const u64 p12 = pack2(w11.x, w11.y), p13 = pack2(w11.z, w11.w);
            const u64 vAx = pack2(vA.x, vA.x), vAy = pack2(vA.y, vA.y);
            const u64 vBx = pack2(vB.x, vB.x), vBy = pack2(vB.y, vB.y);
            aA[0] = ffma2(vAx, p00, aA[0]); aA[1] = ffma2(vAx, p01, aA[1]);
            aA[2] = ffma2(vAx, p02, aA[2]); aA[3] = ffma2(vAx, p03, aA[3]);
            aB[0] = ffma2(vBx, p00, aB[0]); aB[1] = ffma2(vBx, p01, aB[1]);
            aB[2] = ffma2(vBx, p02, aB[2]); aB[3] = ffma2(vBx, p03, aB[3]);
            aA[0] = ffma2(vAy, p10, aA[0]); aA[1] = ffma2(vAy, p11, aA[1]);
            aA[2] = ffma2(vAy, p12, aA[2]); aA[3] = ffma2(vAy, p13, aA[3]);
            aB[0] = ffma2(vBy, p10, aB[0]); aB[1] = ffma2(vBy, p11, aB[1]);
            aB[2] = ffma2(vBy, p12, aB[2]); aB[3] = ffma2(vBy, p13, aB[3]);
        }
        #pragma unroll
        for (int j = 0; j < 4; j++) {
            float x, y; unpack2(aA[j], x, y);
            *(float2*)(zout + n0 * 34 + o0 + 2 * j) =
                make_float2(fmaxf(x, 0.f), fmaxf(y, 0.f));
        }
        #pragma unroll
        for (int j = 0; j < 4; j++) {
            float x, y; unpack2(aB[j], x, y);
            *(float2*)(zout + n1 * 34 + o0 + 2 * j) =
                make_float2(fmaxf(x, 0.f), fmaxf(y, 0.f));
        }
    }
}

__global__ void __launch_bounds__(256, 4)
seal_kernel(
    const int* __restrict__ labels,
    const int* __restrict__ src,
    const int* __restrict__ dst,
    const float* __restrict__ emb,
    const float* __restrict__ w1_0, const float* __restrict__ b1_0,
    const float* __restrict__ w2_0, const float* __restrict__ b2_0,
    const float* __restrict__ w1_1, const float* __restrict__ b1_1,
    const float* __restrict__ w2_1, const float* __restrict__ b2_1,
    const float* __restrict__ w1_2, const float* __restrict__ b1_2,
    const float* __restrict__ w2_2, const float* __restrict__ b2_2,
    const float* __restrict__ conv1_w, const float* __restrict__ conv1_b,
    const float* __restrict__ conv2_w, const float* __restrict__ conv2_b,
    const float* __restrict__ sc_w1, const float* __restrict__ sc_b1,
    const float* __restrict__ sc_w2, const float* __restrict__ sc_b2,
    float* __restrict__ out)
{
    // pool union:
    //   GIN phase : bufA[64*34] | bufB[64*34] | wbuf[2112] (w1@0 b1@1024 w2@1056 b2@2080)
    //   conv1     : weights stride-165 (32*165=5280) + bias @5280
    //   conv2     : weights stride-165 (16*165=2640) + bias @2640 + scorer @2660..2960
    __shared__ float pool[6464];
    __shared__ int   starts[65];
    __shared__ int   cursor[64];
    __shared__ unsigned short esrc[1024];
    __shared__ float pooled[10 * 33];
    __shared__ float ybuf[32 * 5];
    __shared__ float c2buf[16 * 5];
    __shared__ float feat[16];
    __shared__ float hidbuf[16];
    __shared__ int   nodeOfRank[10];

    float* bufA = pool;
    float* bufB = pool + 2176;
    float* wbuf = pool + 4352;

    const int g = blockIdx.x;
    const int t = threadIdx.x;
    const int lane = t & 31;

    // ------------------------------------------------------------------
    // CSR build keyed by destination; match-based atomic dedup
    // ------------------------------------------------------------------
    if (t < 64) cursor[t] = 0;
    __syncthreads();

    int es[4], ed[4];
    unsigned msk[4];
    const int* gsrc = src + (g << 10);
    const int* gdst = dst + (g << 10);
    #pragma unroll
    for (int i = 0; i < 4; i++) {
        es[i] = gsrc[t + i * 256] & 63;
        ed[i] = gdst[t + i * 256] & 63;
    }
    #pragma unroll
    for (int i = 0; i < 4; i++) {
        msk[i] = __match_any_sync(0xffffffffu, ed[i]);
        const int leader = __ffs(msk[i]) - 1;
        if (lane == leader) atomicAdd(&cursor[ed[i]], __popc(msk[i]));
    }
    __syncthreads();

    if (t < 32) {  // warp 0: exclusive prefix over 64 bins (2 per lane)
        const int c0 = cursor[2 * t], c1 = cursor[2 * t + 1];
        const int s = c0 + c1;
        int incl = s;
        #pragma unroll
        for (int d = 1; d < 32; d <<= 1) {
            const int v = __shfl_up_sync(0xffffffffu, incl, d);
            if (t >= d) incl += v;
        }
        const int ex = incl - s;
        starts[2 * t] = ex;      starts[2 * t + 1] = ex + c0;
        cursor[2 * t] = ex;      cursor[2 * t + 1] = ex + c0;
        if (t == 31) starts[64] = incl;
    }
    __syncthreads();

    #pragma unroll
    for (int i = 0; i < 4; i++) {
        const int leader = __ffs(msk[i]) - 1;
        const int rank = __popc(msk[i] & ((1u << lane) - 1u));
        int base = 0;
        if (lane == leader) base = atomicAdd(&cursor[ed[i]], __popc(msk[i]));
        base = __shfl_sync(0xffffffffu, base, leader);
        esrc[base + rank] = (unsigned short)es[i];
    }

    // ------------------------------------------------------------------
    // DRNL embedding -> bufA (64 x 16, stride 34)
    // ------------------------------------------------------------------
    const int* glab = labels + (g << 6);
    for (int idx = t; idx < 1024; idx += 256) {
        const int n = idx >> 4, c = idx & 15;
        bufA[n * 34 + c] = emb[glab[n] * 16 + c];
    }
    __syncthreads();

    const float* W1s[3] = { w1_0, w1_1, w1_2 };
    const float* B1s[3] = { b1_0, b1_1, b1_2 };
    const float* W2s[3] = { w2_0, w2_1, w2_2 };
    const float* B2s[3] = { b2_0, b2_1, b2_2 };

    float* cur = bufA;
    float* oth = bufB;

    // ------------------------------------------------------------------
    // 3 GIN layers
    // ------------------------------------------------------------------
    for (int l = 0; l < 3; l++) {
        const int din = l ? 32 : 16;

        for (int idx = t; idx < din * 32; idx += 256) wbuf[idx] = W1s[l][idx];
        if (t < 32)            wbuf[1024 + t] = B1s[l][t];
        for (int idx = t; idx < 1024; idx += 256) wbuf[1056 + idx] = W2s[l][idx];
        if (t >= 32 && t < 64) wbuf[2080 + (t - 32)] = B2s[l][t - 32];
        __syncthreads();

        // ---- aggregation: warp per 8 nodes, lane = channel ----
        {
            const int w = t >> 5;
            for (int n = w * 8; n < w * 8 + 8; n++) {
                const int e0 = starts[n], e1 = starts[n + 1];
                float a0 = cur[n * 34 + lane], a1 = 0.f;
                int e = e0;
                for (; e + 2 <= e1; e += 2) {
                    a0 += cur[esrc[e] * 34 + lane];
                    a1 += cur[esrc[e + 1] * 34 + lane];
                }
                if (e < e1) a0 += cur[esrc[e] * 34 + lane];
                oth[n * 34 + lane] = a0 + a1;
            }
        }
        __syncthreads();
        { float* tmp = cur; cur = oth; oth = tmp; }

        gemm_relu(cur, oth, wbuf, wbuf + 1024, din, t);
        __syncthreads();
        { float* tmp = cur; cur = oth; oth = tmp; }

        gemm_relu(cur, oth, wbuf + 1056, wbuf + 2080, 32, t);
        __syncthreads();
        { float* tmp = cur; cur = oth; oth = tmp; }
    }

    // ------------------------------------------------------------------
    // SortPooling: stable rank by channel 31 descending, keep 10
    // ------------------------------------------------------------------
    if (t < 64) {
        const float key = cur[t * 34 + 31];
        int r = 0;
        for (int m = 0; m < 64; m++) {
            const float km = cur[m * 34 + 31];
            r += (km > key) || (km == key && m < t);
        }
        if (r < 10) nodeOfRank[r] = t;
    }
    __syncthreads();
    for (int idx = t; idx < 10 * 32; idx += 256) {
        const int k = idx >> 5, c = idx & 31;
        pooled[k * 33 + c] = cur[nodeOfRank[k] * 34 + c];
    }
    __syncthreads();

    // ------------------------------------------------------------------
    // Conv1 (32->32, k=5, pad=2) + ReLU fused with MaxPool1d(2,2)
    // ------------------------------------------------------------------
    for (int idx = t; idx < 32 * 160; idx += 256) {
        const int co = idx / 160, r = idx - co * 160;
        pool[co * 165 + r] = conv1_w[idx];
    }
    if (t < 32) pool[5280 + t] = conv1_b[t];
    __syncthreads();

    if (t < 160) {
        const int co = t & 31, q = t >> 5;
        float a0 = pool[5280 + co];
        float a1 = a0;
        const float* wrow = pool + co * 165;
        for (int ci = 0; ci < 32; ci++) {
            #pragma unroll
            for (int k = 0; k < 5; k++) {
                const float w = wrow[ci * 5 + k];
                const int p0 = 2 * q + k - 2;
                const int p1 = p0 + 1;
                if (p0 >= 0 && p0 < 10) a0 += w * pooled[p0 * 33 + ci];
                if (p1 >= 0 && p1 < 10) a1 += w * pooled[p1 * 33 + ci];
            }
        }
        ybuf[co * 5 + q] = fmaxf(fmaxf(a0, 0.f), fmaxf(a1, 0.f));
    }
    __syncthreads();

    // ------------------------------------------------------------------
    // Conv2 (32->16, k=5, pad=2) + ReLU, mean, scorer MLP
    // ------------------------------------------------------------------
    for (int idx = t; idx < 16 * 160; idx += 256) {
        const int co = idx / 160, r = idx - co * 160;
        pool[co * 165 + r] = conv2_w[idx];
    }
    if (t < 16)                pool[2640 + t] = conv2_b[t];
    for (int idx = t; idx < 256; idx += 256) pool[2660 + idx] = sc_w1[idx];
    if (t < 16)                pool[2920 + t] = sc_b1[t];
    if (t >= 16 && t < 32)     pool[2940 + (t - 16)] = sc_w2[t - 16];
    if (t == 32)               pool[2960] = sc_b2[0];
    __syncthreads();

    if (t < 80) {
        const int co = t & 15, p = t >> 4;
        float a = pool[2640 + co];
        const float* wrow = pool + co * 165;
        for (int ci = 0; ci < 32; ci++) {
            #pragma unroll
            for (int k = 0; k < 5; k++) {
                const int q = p + k - 2;
                if (q >= 0 && q < 5) a += wrow[ci * 5 + k] * ybuf[ci * 5 + q];
            }
        }
        c2buf[co * 5 + p] = fmaxf(a, 0.f);
    }
    __syncthreads();

    if (t < 16) {
        feat[t] = 0.2f * (c2buf[t * 5 + 0] + c2buf[t * 5 + 1] + c2buf[t * 5 + 2] +
                          c2buf[t * 5 + 3] + c2buf[t * 5 + 4]);
    }
    __syncthreads();

    if (t < 16) {
        float a = pool[2920 + t];
        #pragma unroll
        for (int i = 0; i < 16; i++) a += feat[i] * pool[2660 + i * 16 + t];
        hidbuf[t] = fmaxf(a, 0.f);
    }
    __syncthreads();

    if (t == 0) {
        float s = pool[2960];
        #pragma unroll
        for (int j = 0; j < 16; j++) s += hidbuf[j] * pool[2940 + j];
        out[g] = s;
    }
}

extern "C" void kernel_launch(void* const* d_in, const int* in_sizes, int n_in,
                              void* d_out, int out_size)
{
    const int B = in_sizes[0] / 64;
    seal_kernel<<<B, 256>>>(
        (const int*)d_in[0], (const int*)d_in[1], (const int*)d_in[2],
        (const float*)d_in[3],
        (const float*)d_in[4],  (const float*)d_in[5],
        (const float*)d_in[6],  (const float*)d_in[7],
        (const float*)d_in[8],  (const float*)d_in[9],
        (const float*)d_in[10], (const float*)d_in[11],
        (const float*)d_in[12], (const float*)d_in[13],
        (const float*)d_in[14], (const float*)d_in[15],
        (const float*)d_in[16], (const float*)d_in[17],
        (const float*)d_in[18], (const float*)d_in[19],
        (const float*)d_in[20], (const float*)d_in[21],
        (const float*)d_in[22], (const float*)d_in[23],
        (float*)d_out);
}

// round 3
// speedup vs baseline: 1.4953x; 1.0858x over previous
#include <cuda_runtime.h>

typedef unsigned long long u64;

__device__ __forceinline__ u64 pack2(float x, float y) {
    u64 r; asm("mov.b64 %0, {%1, %2};" : "=l"(r) : "f"(x), "f"(y)); return r;
}
__device__ __forceinline__ void unpack2(u64 v, float& x, float& y) {
    asm("mov.b64 {%0, %1}, %2;" : "=f"(x), "=f"(y) : "l"(v));
}
__device__ __forceinline__ u64 ffma2(u64 a, u64 b, u64 c) {
    u64 d; asm("fma.rn.f32x2 %0, %1, %2, %3;" : "=l"(d) : "l"(a), "l"(b), "l"(c));
    return d;
}

#define HSTR 36   // node-feature row stride (floats); 36*4=144 -> 16B aligned rows
#define ASTR 66   // adjacency row stride

// Dense aggregation: Z[n][o] = H[n][o] + sum_k A[n][k] * H[k][o]
// NOUT = 16 or 32. Threads: 32*NOUT/8 (64 or 128). No relu.
template<int NOUT>
__device__ __forceinline__ void agg_gemm(const float* __restrict__ H,
                                         float* __restrict__ Z,
                                         const float* __restrict__ A, int t)
{
    constexpr int OG = NOUT / 8;
    if (t < 32 * OG) {
        const int o0 = (t & (OG - 1)) * 8;
        const int n0 = (t / OG) * 2, n1 = n0 + 1;
        u64 aA[4], aB[4];
        {   // accumulator init = self term h[n]
            const float4 s0 = *(const float4*)(H + n0 * HSTR + o0);
            const float4 s1 = *(const float4*)(H + n0 * HSTR + o0 + 4);
            const float4 s2 = *(const float4*)(H + n1 * HSTR + o0);
            const float4 s3 = *(const float4*)(H + n1 * HSTR + o0 + 4);
            aA[0] = pack2(s0.x, s0.y); aA[1] = pack2(s0.z, s0.w);
            aA[2] = pack2(s1.x, s1.y); aA[3] = pack2(s1.z, s1.w);
            aB[0] = pack2(s2.x, s2.y); aB[1] = pack2(s2.z, s2.w);
            aB[2] = pack2(s3.x, s3.y); aB[3] = pack2(s3.z, s3.w);
        }
        const float* rA = A + n0 * ASTR;
        const float* rB = A + n1 * ASTR;
        #pragma unroll 4
        for (int k = 0; k < 64; k += 2) {
            const float2 vA = *(const float2*)(rA + k);
            const float2 vB = *(const float2*)(rB + k);
            const float4 w00 = *(const float4*)(H + k * HSTR + o0);
            const float4 w01 = *(const float4*)(H + k * HSTR + o0 + 4);
            const float4 w10 = *(const float4*)(H + (k + 1) * HSTR + o0);
            const float4 w11 = *(const float4*)(H + (k + 1) * HSTR + o0 + 4);
            const u64 p00 = pack2(w00.x, w00.y), p01 = pack2(w00.z, w00.w);
            const u64 p02 = pack2(w01.x, w01.y), p03 = pack2(w01.z, w01.w);
            const u64 p10 = pack2(w10.x, w10.y), p11 = pack2(w10.z, w10.w);
            const u64 p12 = pack2(w11.x, w11.y), p13 = pack2(w11.z, w11.w);
            const u64 vAx = pack2(vA.x, vA.x), vAy = pack2(vA.y, vA.y);
            const u64 vBx = pack2(vB.x, vB.x), vBy = pack2(vB.y, vB.y);
            aA[0] = ffma2(vAx, p00, aA[0]); aA[1] = ffma2(vAx, p01, aA[1]);
            aA[2] = ffma2(vAx, p02, aA[2]); aA[3] = ffma2(vAx, p03, aA[3]);
            aB[0] = ffma2(vBx, p00, aB[0]); aB[1] = ffma2(vBx, p01, aB[1]);
            aB[2] = ffma2(vBx, p02, aB[2]); aB[3] = ffma2(vBx, p03, aB[3]);
            aA[0] = ffma2(vAy, p10, aA[0]); aA[1] = ffma2(vAy, p11, aA[1]);
            aA[2] = ffma2(vAy, p12, aA[2]); aA[3] = ffma2(vAy, p13, aA[3]);
            aB[0] = ffma2(vBy, p10, aB[0]); aB[1] = ffma2(vBy, p11, aB[1]);
            aB[2] = ffma2(vBy, p12, aB[2]); aB[3] = ffma2(vBy, p13, aB[3]);
        }
        float x0, y0, x1, y1;
        unpack2(aA[0], x0, y0); unpack2(aA[1], x1, y1);
        *(float4*)(Z + n0 * HSTR + o0)     = make_float4(x0, y0, x1, y1);
        unpack2(aA[2], x0, y0); unpack2(aA[3], x1, y1);
        *(float4*)(Z + n0 * HSTR + o0 + 4) = make_float4(x0, y0, x1, y1);
        unpack2(aB[0], x0, y0); unpack2(aB[1], x1, y1);
        *(float4*)(Z + n1 * HSTR + o0)     = make_float4(x0, y0, x1, y1);
        unpack2(aB[2], x0, y0); unpack2(aB[3], x1, y1);
        *(float4*)(Z + n1 * HSTR + o0 + 4) = make_float4(x0, y0, x1, y1);
    }
}

// zout[n,o] = relu(bias[o] + sum_k zin[n,k] * W[k,o]); 64 nodes, 32 outs.
__device__ __forceinline__ void gemm_relu(const float* __restrict__ zin,
                                          float* __restrict__ zout,
                                          const float* __restrict__ W,
                                          const float* __restrict__ bias,
                                          int din, int t)
{
    if (t < 128) {
        const int n0 = (t >> 2) * 2, n1 = n0 + 1;
        const int o0 = (t & 3) * 8;
        const float* wb = W + o0;
        u64 aA[4], aB[4];
        {
            const float4 b0 = *(const float4*)(bias + o0);
            const float4 b1 = *(const float4*)(bias + o0 + 4);
            aA[0] = pack2(b0.x, b0.y); aA[1] = pack2(b0.z, b0.w);
            aA[2] = pack2(b1.x, b1.y); aA[3] = pack2(b1.z, b1.w);
            aB[0] = aA[0]; aB[1] = aA[1]; aB[2] = aA[2]; aB[3] = aA[3];
        }
        const float* zA = zin + n0 * HSTR;
        const float* zB = zin + n1 * HSTR;
        for (int k = 0; k < din; k += 2) {
            const float2 vA = *(const float2*)(zA + k);
            const float2 vB = *(const float2*)(zB + k);
            const float4 w00 = *(const float4*)(wb + k * 32);
            const float4 w01 = *(const float4*)(wb + k * 32 + 4);
            const float4 w10 = *(const float4*)(wb + (k + 1) * 32);
            const float4 w11 = *(const float4*)(wb + (k + 1) * 32 + 4);
            const u64 p00 = pack2(w00.x, w00.y), p01 = pack2(w00.z, w00.w);
            const u64 p02 = pack2(w01.x, w01.y), p03 = pack2(w01.z, w01.w);
            const u64 p10 = pack2(w10.x, w10.y), p11 = pack2(w10.z, w10.w);
            const u64 p12 = pack2(w11.x, w11.y), p13 = pack2(w11.z, w11.w);
            const u64 vAx = pack2(vA.x, vA.x), vAy = pack2(vA.y, vA.y);
            const u64 vBx = pack2(vB.x, vB.x), vBy = pack2(vB.y, vB.y);
            aA[0] = ffma2(vAx, p00, aA[0]); aA[1] = ffma2(vAx, p01, aA[1]);
            aA[2] = ffma2(vAx, p02, aA[2]); aA[3] = ffma2(vAx, p03, aA[3]);
            aB[0] = ffma2(vBx, p00, aB[0]); aB[1] = ffma2(vBx, p01, aB[1]);
            aB[2] = ffma2(vBx, p02, aB[2]); aB[3] = ffma2(vBx, p03, aB[3]);
            aA[0] = ffma2(vAy, p10, aA[0]); aA[1] = ffma2(vAy, p11, aA[1]);
            aA[2] = ffma2(vAy, p12, aA[2]); aA[3] = ffma2(vAy, p13, aA[3]);
            aB[0] = ffma2(vBy, p10, aB[0]); aB[1] = ffma2(vBy, p11, aB[1]);
            aB[2] = ffma2(vBy, p12, aB[2]); aB[3] = ffma2(vBy, p13, aB[3]);
        }
        float x0, y0, x1, y1;
        unpack2(aA[0], x0, y0); unpack2(aA[1], x1, y1);
        *(float4*)(zout + n0 * HSTR + o0) =
            make_float4(fmaxf(x0,0.f), fmaxf(y0,0.f), fmaxf(x1,0.f), fmaxf(y1,0.f));
        unpack2(aA[2], x0, y0); unpack2(aA[3], x1, y1);
        *(float4*)(zout + n0 * HSTR + o0 + 4) =
            make_float4(fmaxf(x0,0.f), fmaxf(y0,0.f), fmaxf(x1,0.f), fmaxf(y1,0.f));
        unpack2(aB[0], x0, y0); unpack2(aB[1], x1, y1);
        *(float4*)(zout + n1 * HSTR + o0) =
            make_float4(fmaxf(x0,0.f), fmaxf(y0,0.f), fmaxf(x1,0.f), fmaxf(y1,0.f));
        unpack2(aB[2], x0, y0); unpack2(aB[3], x1, y1);
        *(float4*)(zout + n1 * HSTR + o0 + 4) =
            make_float4(fmaxf(x0,0.f), fmaxf(y0,0.f), fmaxf(x1,0.f), fmaxf(y1,0.f));
    }
}

__global__ void __launch_bounds__(256, 4)
seal_kernel(
    const int* __restrict__ labels,
    const int* __restrict__ src,
    const int* __restrict__ dst,
    const float* __restrict__ emb,
    const float* __restrict__ w1_0, const float* __restrict__ b1_0,
    const float* __restrict__ w2_0, const float* __restrict__ b2_0,
    const float* __restrict__ w1_1, const float* __restrict__ b1_1,
    const float* __restrict__ w2_1, const float* __restrict__ b2_1,
    const float* __restrict__ w1_2, const float* __restrict__ b1_2,
    const float* __restrict__ w2_2, const float* __restrict__ b2_2,
    const float* __restrict__ conv1_w, const float* __restrict__ conv1_b,
    const float* __restrict__ conv2_w, const float* __restrict__ conv2_b,
    const float* __restrict__ sc_w1, const float* __restrict__ sc_b1,
    const float* __restrict__ sc_w2, const float* __restrict__ sc_b2,
    float* __restrict__ out)
{
    // pool union:
    //  GIN phase : A[64*66=4224] | bufA[64*36=2304]@4224 | bufB@6528 | wbuf[2112]@8832
    //  conv1     : weights stride-165 (5280) + bias @5280   (overwrites A/bufA region; cur=bufB)
    //  conv2     : weights stride-165 (2640) + bias @2640 + scorer @2660..2960
    __shared__ float pool[10944];
    __shared__ float pooled[10 * 33];
    __shared__ float ybuf[32 * 5];
    __shared__ float c2buf[16 * 5];
    __shared__ float feat[16];
    __shared__ float hidbuf[16];
    __shared__ int   nodeOfRank[10];

    float* A    = pool;
    float* bufA = pool + 4224;
    float* bufB = pool + 6528;
    float* wbuf = pool + 8832;

    const int g = blockIdx.x;
    const int t = threadIdx.x;

    // ------------------------------------------------------------------
    // Dense adjacency build: A[dst][src] += 1
    // ------------------------------------------------------------------
    {
        float4 z4 = make_float4(0.f, 0.f, 0.f, 0.f);
        for (int idx = t; idx < 4224 / 4; idx += 256)
            *(float4*)(A + idx * 4) = z4;
    }
    __syncthreads();
    {
        const int4 s4 = ((const int4*)(src + (g << 10)))[t];
        const int4 d4 = ((const int4*)(dst + (g << 10)))[t];
        atomicAdd(&A[(d4.x & 63) * ASTR + (s4.x & 63)], 1.0f);
        atomicAdd(&A[(d4.y & 63) * ASTR + (s4.y & 63)], 1.0f);
        atomicAdd(&A[(d4.z & 63) * ASTR + (s4.z & 63)], 1.0f);
        atomicAdd(&A[(d4.w & 63) * ASTR + (s4.w & 63)], 1.0f);
    }

    // ------------------------------------------------------------------
    // DRNL embedding -> bufA (64 x 16, stride HSTR)
    // ------------------------------------------------------------------
    {
        const int* glab = labels + (g << 6);
        const int n = t >> 2, c = (t & 3) * 4;
        const float4 v = *(const float4*)(emb + glab[n] * 16 + c);
        *(float4*)(bufA + n * HSTR + c) = v;
    }
    __syncthreads();

    const float* W1s[3] = { w1_0, w1_1, w1_2 };
    const float* B1s[3] = { b1_0, b1_1, b1_2 };
    const float* W2s[3] = { w2_0, w2_1, w2_2 };
    const float* B2s[3] = { b2_0, b2_1, b2_2 };

    float* cur = bufA;
    float* oth = bufB;

    // ------------------------------------------------------------------
    // 3 GIN layers: h = relu(relu((h + A@h) @ W1 + b1) @ W2 + b2)
    // ------------------------------------------------------------------
    for (int l = 0; l < 3; l++) {
        const int din = l ? 32 : 16;

        for (int idx = t; idx < din * 8; idx += 256)
            *(float4*)(wbuf + idx * 4) = *(const float4*)(W1s[l] + idx * 4);
        if (t < 32)            wbuf[1024 + t] = B1s[l][t];
        for (int idx = t; idx < 256; idx += 256)
            *(float4*)(wbuf + 1056 + idx * 4) = *(const float4*)(W2s[l] + idx * 4);
        if (t >= 32 && t < 64) wbuf[2080 + (t - 32)] = B2s[l][t - 32];
        __syncthreads();

        if (l == 0) agg_gemm<16>(cur, oth, A, t);
        else        agg_gemm<32>(cur, oth, A, t);
        __syncthreads();
        { float* tmp = cur; cur = oth; oth = tmp; }

        gemm_relu(cur, oth, wbuf, wbuf + 1024, din, t);
        __syncthreads();
        { float* tmp = cur; cur = oth; oth = tmp; }

        gemm_relu(cur, oth, wbuf + 1056, wbuf + 2080, 32, t);
        __syncthreads();
        { float* tmp = cur; cur = oth; oth = tmp; }
    }
    // cur == bufB here (9 swaps)

    // ------------------------------------------------------------------
    // SortPooling: stable rank by channel 31 descending, keep 10
    // ------------------------------------------------------------------
    if (t < 64) {
        const float key = cur[t * HSTR + 31];
        int r = 0;
        for (int m = 0; m < 64; m++) {
            const float km = cur[m * HSTR + 31];
            r += (km > key) || (km == key && m < t);
        }
        if (r < 10) nodeOfRank[r] = t;
    }
    __syncthreads();
    for (int idx = t; idx < 10 * 32; idx += 256) {
        const int k = idx >> 5, c = idx & 31;
        pooled[k * 33 + c] = cur[nodeOfRank[k] * HSTR + c];
    }
    __syncthreads();

    // ------------------------------------------------------------------
    // Conv1 (32->32, k=5, pad=2) + ReLU fused with MaxPool1d(2,2)
    // ------------------------------------------------------------------
    for (int idx = t; idx < 32 * 160; idx += 256) {
        const int co = idx / 160, r = idx - co * 160;
        pool[co * 165 + r] = conv1_w[idx];
    }
    if (t < 32) pool[5280 + t] = conv1_b[t];
    __syncthreads();

    if (t < 160) {
        const int co = t & 31, q = t >> 5;
        float a0 = pool[5280 + co];
        float a1 = a0;
        const float* wrow = pool + co * 165;
        for (int ci = 0; ci < 32; ci++) {
            #pragma unroll
            for (int k = 0; k < 5; k++) {
                const float w = wrow[ci * 5 + k];
                const int p0 = 2 * q + k - 2;
                const int p1 = p0 + 1;
                if (p0 >= 0 && p0 < 10) a0 += w * pooled[p0 * 33 + ci];
                if (p1 >= 0 && p1 < 10) a1 += w * pooled[p1 * 33 + ci];
            }
        }
        ybuf[co * 5 + q] = fmaxf(fmaxf(a0, 0.f), fmaxf(a1, 0.f));
    }
    __syncthreads();

    // ------------------------------------------------------------------
    // Conv2 (32->16, k=5, pad=2) + ReLU, mean, scorer MLP
    // ------------------------------------------------------------------
    for (int idx = t; idx < 16 * 160; idx += 256) {
        const int co = idx / 160, r = idx - co * 160;
        pool[co * 165 + r] = conv2_w[idx];
    }
    if (t < 16)                pool[2640 + t] = conv2_b[t];
    for (int idx = t; idx < 256; idx += 256) pool[2660 + idx] = sc_w1[idx];
    if (t < 16)                pool[2920 + t] = sc_b1[t];
    if (t >= 16 && t < 32)     pool[2940 + (t - 16)] = sc_w2[t - 16];
    if (t == 32)               pool[2960] = sc_b2[0];
    __syncthreads();

    if (t < 80) {
        const int co = t & 15, p = t >> 4;
        float a = pool[2640 + co];
        const float* wrow = pool + co * 165;
        for (int ci = 0; ci < 32; ci++) {
            #pragma unroll
            for (int k = 0; k < 5; k++) {
                const int q = p + k - 2;
                if (q >= 0 && q < 5) a += wrow[ci * 5 + k] * ybuf[ci * 5 + q];
            }
        }
        c2buf[co * 5 + p] = fmaxf(a, 0.f);
    }
    __syncthreads();

    if (t < 16) {
        feat[t] = 0.2f * (c2buf[t * 5 + 0] + c2buf[t * 5 + 1] + c2buf[t * 5 + 2] +
                          c2buf[t * 5 + 3] + c2buf[t * 5 + 4]);
    }
    __syncthreads();

    if (t < 16) {
        float a = pool[2920 + t];
        #pragma unroll
        for (int i = 0; i < 16; i++) a += feat[i] * pool[2660 + i * 16 + t];
        hidbuf[t] = fmaxf(a, 0.f);
    }
    __syncthreads();

    if (t == 0) {
        float s = pool[2960];
        #pragma unroll
        for (int j = 0; j < 16; j++) s += hidbuf[j] * pool[2940 + j];
        out[g] = s;
    }
}

extern "C" void kernel_launch(void* const* d_in, const int* in_sizes, int n_in,
                              void* d_out, int out_size)
{
    const int B = in_sizes[0] / 64;
    seal_kernel<<<B, 256>>>(
        (const int*)d_in[0], (const int*)d_in[1], (const int*)d_in[2],
        (const float*)d_in[3],
        (const float*)d_in[4],  (const float*)d_in[5],
        (const float*)d_in[6],  (const float*)d_in[7],
        (const float*)d_in[8],  (const float*)d_in[9],
        (const float*)d_in[10], (const float*)d_in[11],
        (const float*)d_in[12], (const float*)d_in[13],
        (const float*)d_in[14], (const float*)d_in[15],
        (const float*)d_in[16], (const float*)d_in[17],
        (const float*)d_in[18], (const float*)d_in[19],
        (const float*)d_in[20], (const float*)d_in[21],
        (const float*)d_in[22], (const float*)d_in[23],
        (float*)d_out);
}

// round 4
// speedup vs baseline: 1.5021x; 1.0046x over previous
#include <cuda_runtime.h>

typedef unsigned long long u64;

__device__ __forceinline__ u64 pack2(float x, float y) {
    u64 r; asm("mov.b64 %0, {%1, %2};" : "=l"(r) : "f"(x), "f"(y)); return r;
}
__device__ __forceinline__ void unpack2(u64 v, float& x, float& y) {
    asm("mov.b64 {%0, %1}, %2;" : "=f"(x), "=f"(y) : "l"(v));
}
__device__ __forceinline__ u64 ffma2(u64 a, u64 b, u64 c) {
    u64 d; asm("fma.rn.f32x2 %0, %1, %2, %3;" : "=l"(d) : "l"(a), "l"(b), "l"(c));
    return d;
}

#define HSTR 36   // node-feature row stride (floats); 36*4=144 -> 16B aligned rows
#define ASTR 66   // adjacency row stride

// Dense aggregation: Z[n][o] = H[n][o] + sum_k A[n][k] * H[k][o]
// NOUT = 16 or 32. Threads: 32*NOUT/8 (64 or 128). No relu.
template<int NOUT>
__device__ __forceinline__ void agg_gemm(const float* __restrict__ H,
                                         float* __restrict__ Z,
                                         const float* __restrict__ A, int t)
{
    constexpr int OG = NOUT / 8;
    if (t < 32 * OG) {
        const int o0 = (t & (OG - 1)) * 8;
        const int n0 = (t / OG) * 2, n1 = n0 + 1;
        u64 aA[4], aB[4];
        {   // accumulator init = self term h[n]
            const float4 s0 = *(const float4*)(H + n0 * HSTR + o0);
            const float4 s1 = *(const float4*)(H + n0 * HSTR + o0 + 4);
            const float4 s2 = *(const float4*)(H + n1 * HSTR + o0);
            const float4 s3 = *(const float4*)(H + n1 * HSTR + o0 + 4);
            aA[0] = pack2(s0.x, s0.y); aA[1] = pack2(s0.z, s0.w);
            aA[2] = pack2(s1.x, s1.y); aA[3] = pack2(s1.z, s1.w);
            aB[0] = pack2(s2.x, s2.y); aB[1] = pack2(s2.z, s2.w);
            aB[2] = pack2(s3.x, s3.y); aB[3] = pack2(s3.z, s3.w);
        }
        const float* rA = A + n0 * ASTR;
        const float* rB = A + n1 * ASTR;
        #pragma unroll 4
        for (int k = 0; k < 64; k += 2) {
            const float2 vA = *(const float2*)(rA + k);
            const float2 vB = *(const float2*)(rB + k);
            const float4 w00 = *(const float4*)(H + k * HSTR + o0);
            const float4 w01 = *(const float4*)(H + k * HSTR + o0 + 4);
            const float4 w10 = *(const float4*)(H + (k + 1) * HSTR + o0);
            const float4 w11 = *(const float4*)(H + (k + 1) * HSTR + o0 + 4);
            const u64 p00 = pack2(w00.x, w00.y), p01 = pack2(w00.z, w00.w);
            const u64 p02 = pack2(w01.x, w01.y), p03 = pack2(w01.z, w01.w);
            const u64 p10 = pack2(w10.x, w10.y), p11 = pack2(w10.z, w10.w);
            const u64 p12 = pack2(w11.x, w11.y), p13 = pack2(w11.z, w11.w);
            const u64 vAx = pack2(vA.x, vA.x), vAy = pack2(vA.y, vA.y);
            const u64 vBx = pack2(vB.x, vB.x), vBy = pack2(vB.y, vB.y);
            aA[0] = ffma2(vAx, p00, aA[0]); aA[1] = ffma2(vAx, p01, aA[1]);
            aA[2] = ffma2(vAx, p02, aA[2]); aA[3] = ffma2(vAx, p03, aA[3]);
            aB[0] = ffma2(vBx, p00, aB[0]); aB[1] = ffma2(vBx, p01, aB[1]);
            aB[2] = ffma2(vBx, p02, aB[2]); aB[3] = ffma2(vBx, p03, aB[3]);
            aA[0] = ffma2(vAy, p10, aA[0]); aA[1] = ffma2(vAy, p11, aA[1]);
            aA[2] = ffma2(vAy, p12, aA[2]); aA[3] = ffma2(vAy, p13, aA[3]);
            aB[0] = ffma2(vBy, p10, aB[0]); aB[1] = ffma2(vBy, p11, aB[1]);
            aB[2] = ffma2(vBy, p12, aB[2]); aB[3] = ffma2(vBy, p13, aB[3]);
        }
        float x0, y0, x1, y1;
        unpack2(aA[0], x0, y0); unpack2(aA[1], x1, y1);
        *(float4*)(Z + n0 * HSTR + o0)     = make_float4(x0, y0, x1, y1);
        unpack2(aA[2], x0, y0); unpack2(aA[3], x1, y1);
        *(float4*)(Z + n0 * HSTR + o0 + 4) = make_float4(x0, y0, x1, y1);
        unpack2(aB[0], x0, y0); unpack2(aB[1], x1, y1);
        *(float4*)(Z + n1 * HSTR + o0)     = make_float4(x0, y0, x1, y1);
        unpack2(aB[2], x0, y0); unpack2(aB[3], x1, y1);
        *(float4*)(Z + n1 * HSTR + o0 + 4) = make_float4(x0, y0, x1, y1);
    }
}

// zout[n,o] = relu(bias[o] + sum_k zin[n,k] * W[k,o]); 64 nodes, 32 outs.
__device__ __forceinline__ void gemm_relu(const float* __restrict__ zin,
                                          float* __restrict__ zout,
                                          const float* __restrict__ W,
                                          const float* __restrict__ bias,
                                          int din, int t)
{
    if (t < 128) {
        const int n0 = (t >> 2) * 2, n1 = n0 + 1;
        const int o0 = (t & 3) * 8;
        const float* wb = W + o0;
        u64 aA[4], aB[4];
        {
            const float4 b0 = *(const float4*)(bias + o0);
            const float4 b1 = *(const float4*)(bias + o0 + 4);
            aA[0] = pack2(b0.x, b0.y); aA[1] = pack2(b0.z, b0.w);
            aA[2] = pack2(b1.x, b1.y); aA[3] = pack2(b1.z, b1.w);
            aB[0] = aA[0]; aB[1] = aA[1]; aB[2] = aA[2]; aB[3] = aA[3];
        }
        const float* zA = zin + n0 * HSTR;
        const float* zB = zin + n1 * HSTR;
        for (int k = 0; k < din; k += 2) {
            const float2 vA = *(const float2*)(zA + k);
            const float2 vB = *(const float2*)(zB + k);
            const float4 w00 = *(const float4*)(wb + k * 32);
            const float4 w01 = *(const float4*)(wb + k * 32 + 4);
            const float4 w10 = *(const float4*)(wb + (k + 1) * 32);
            const float4 w11 = *(const float4*)(wb + (k + 1) * 32 + 4);
            const u64 p00 = pack2(w00.x, w00.y), p01 = pack2(w00.z, w00.w);
            const u64 p02 = pack2(w01.x, w01.y), p03 = pack2(w01.z, w01.w);
            const u64 p10 = pack2(w10.x, w10.y), p11 = pack2(w10.z, w10.w);
            const u64 p12 = pack2(w11.x, w11.y), p13 = pack2(w11.z, w11.w);
            const u64 vAx = pack2(vA.x, vA.x), vAy = pack2(vA.y, vA.y);
            const u64 vBx = pack2(vB.x, vB.x), vBy = pack2(vB.y, vB.y);
            aA[0] = ffma2(vAx, p00, aA[0]); aA[1] = ffma2(vAx, p01, aA[1]);
            aA[2] = ffma2(vAx, p02, aA[2]); aA[3] = ffma2(vAx, p03, aA[3]);
            aB[0] = ffma2(vBx, p00, aB[0]); aB[1] = ffma2(vBx, p01, aB[1]);
            aB[2] = ffma2(vBx, p02, aB[2]); aB[3] = ffma2(vBx, p03, aB[3]);
            aA[0] = ffma2(vAy, p10, aA[0]); aA[1] = ffma2(vAy, p11, aA[1]);
            aA[2] = ffma2(vAy, p12, aA[2]); aA[3] = ffma2(vAy, p13, aA[3]);
            aB[0] = ffma2(vBy, p10, aB[0]); aB[1] = ffma2(vBy, p11, aB[1]);
            aB[2] = ffma2(vBy, p12, aB[2]); aB[3] = ffma2(vBy, p13, aB[3]);
        }
        float x0, y0, x1, y1;
        unpack2(aA[0], x0, y0); unpack2(aA[1], x1, y1);
        *(float4*)(zout + n0 * HSTR + o0) =
            make_float4(fmaxf(x0,0.f), fmaxf(y0,0.f), fmaxf(x1,0.f), fmaxf(y1,0.f));
        unpack2(aA[2], x0, y0); unpack2(aA[3], x1, y1);
        *(float4*)(zout + n0 * HSTR + o0 + 4) =
            make_float4(fmaxf(x0,0.f), fmaxf(y0,0.f), fmaxf(x1,0.f), fmaxf(y1,0.f));
        unpack2(aB[0], x0, y0); unpack2(aB[1], x1, y1);
        *(float4*)(zout + n1 * HSTR + o0) =
            make_float4(fmaxf(x0,0.f), fmaxf(y0,0.f), fmaxf(x1,0.f), fmaxf(y1,0.f));
        unpack2(aB[2], x0, y0); unpack2(aB[3], x1, y1);
        *(float4*)(zout + n1 * HSTR + o0 + 4) =
            make_float4(fmaxf(x0,0.f), fmaxf(y0,0.f), fmaxf(x1,0.f), fmaxf(y1,0.f));
    }
}

__global__ void __launch_bounds__(256, 4)
seal_kernel(
    const int* __restrict__ labels,
    const int* __restrict__ src,
    const int* __restrict__ dst,
    const float* __restrict__ emb,
    const float* __restrict__ w1_0, const float* __restrict__ b1_0,
    const float* __restrict__ w2_0, const float* __restrict__ b2_0,
    const float* __restrict__ w1_1, const float* __restrict__ b1_1,
    const float* __restrict__ w2_1, const float* __restrict__ b2_1,
    const float* __restrict__ w1_2, const float* __restrict__ b1_2,
    const float* __restrict__ w2_2, const float* __restrict__ b2_2,
    const float* __restrict__ conv1_w, const float* __restrict__ conv1_b,
    const float* __restrict__ conv2_w, const float* __restrict__ conv2_b,
    const float* __restrict__ sc_w1, const float* __restrict__ sc_b1,
    const float* __restrict__ sc_w2, const float* __restrict__ sc_b2,
    float* __restrict__ out)
{
    // pool union:
    //  GIN phase : A[64*66=4224] | bufA[64*36=2304]@4224 | bufB@6528 | wbuf[2112]@8832
    //  conv1     : weights stride-165 (5280) + bias @5280   (overwrites A/bufA region; cur=bufB)
    //  conv2     : weights stride-165 (2640) + bias @2640 + scorer @2660..2960
    __shared__ float pool[10944];
    __shared__ float pooled[10 * 33];
    __shared__ float ybuf[32 * 5];
    __shared__ float c2buf[16 * 5];
    __shared__ float feat[16];
    __shared__ float hidbuf[16];
    __shared__ int   nodeOfRank[10];

    float* A    = pool;
    float* bufA = pool + 4224;
    float* bufB = pool + 6528;
    float* wbuf = pool + 8832;

    const int g = blockIdx.x;
    const int t = threadIdx.x;

    // ------------------------------------------------------------------
    // Dense adjacency build: A[dst][src] += 1
    // ------------------------------------------------------------------
    {
        float4 z4 = make_float4(0.f, 0.f, 0.f, 0.f);
        for (int idx = t; idx < 4224 / 4; idx += 256)
            *(float4*)(A + idx * 4) = z4;
    }
    __syncthreads();
    {
        const int4 s4 = ((const int4*)(src + (g << 10)))[t];
        const int4 d4 = ((const int4*)(dst + (g << 10)))[t];
        atomicAdd(&A[(d4.x & 63) * ASTR + (s4.x & 63)], 1.0f);
        atomicAdd(&A[(d4.y & 63) * ASTR + (s4.y & 63)], 1.0f);
        atomicAdd(&A[(d4.z & 63) * ASTR + (s4.z & 63)], 1.0f);
        atomicAdd(&A[(d4.w & 63) * ASTR + (s4.w & 63)], 1.0f);
    }

    // ------------------------------------------------------------------
    // DRNL embedding -> bufA (64 x 16, stride HSTR)
    // ------------------------------------------------------------------
    {
        const int* glab = labels + (g << 6);
        const int n = t >> 2, c = (t & 3) * 4;
        const float4 v = *(const float4*)(emb + glab[n] * 16 + c);
        *(float4*)(bufA + n * HSTR + c) = v;
    }
    __syncthreads();

    const float* W1s[3] = { w1_0, w1_1, w1_2 };
    const float* B1s[3] = { b1_0, b1_1, b1_2 };
    const float* W2s[3] = { w2_0, w2_1, w2_2 };
    const float* B2s[3] = { b2_0, b2_1, b2_2 };

    float* cur = bufA;
    float* oth = bufB;

    // ------------------------------------------------------------------
    // 3 GIN layers: h = relu(relu((h + A@h) @ W1 + b1) @ W2 + b2)
    // ------------------------------------------------------------------
    for (int l = 0; l < 3; l++) {
        const int din = l ? 32 : 16;

        for (int idx = t; idx < din * 8; idx += 256)
            *(float4*)(wbuf + idx * 4) = *(const float4*)(W1s[l] + idx * 4);
        if (t < 32)            wbuf[1024 + t] = B1s[l][t];
        for (int idx = t; idx < 256; idx += 256)
            *(float4*)(wbuf + 1056 + idx * 4) = *(const float4*)(W2s[l] + idx * 4);
        if (t >= 32 && t < 64) wbuf[2080 + (t - 32)] = B2s[l][t - 32];
        __syncthreads();

        if (l == 0) agg_gemm<16>(cur, oth, A, t);
        else        agg_gemm<32>(cur, oth, A, t);
        __syncthreads();
        { float* tmp = cur; cur = oth; oth = tmp; }

        gemm_relu(cur, oth, wbuf, wbuf + 1024, din, t);
        __syncthreads();
        { float* tmp = cur; cur = oth; oth = tmp; }

        gemm_relu(cur, oth, wbuf + 1056, wbuf + 2080, 32, t);
        __syncthreads();
        { float* tmp = cur; cur = oth; oth = tmp; }
    }
    // cur == bufB here (9 swaps)

    // ------------------------------------------------------------------
    // SortPooling: stable rank by channel 31 descending, keep 10
    // ------------------------------------------------------------------
    if (t < 64) {
        const float key = cur[t * HSTR + 31];
        int r = 0;
        for (int m = 0; m < 64; m++) {
            const float km = cur[m * HSTR + 31];
            r += (km > key) || (km == key && m < t);
        }
        if (r < 10) nodeOfRank[r] = t;
    }
    __syncthreads();
    for (int idx = t; idx < 10 * 32; idx += 256) {
        const int k = idx >> 5, c = idx & 31;
        pooled[k * 33 + c] = cur[nodeOfRank[k] * HSTR + c];
    }
    __syncthreads();

    // ------------------------------------------------------------------
    // Conv1 (32->32, k=5, pad=2) + ReLU fused with MaxPool1d(2,2)
    // ------------------------------------------------------------------
    for (int idx = t; idx < 32 * 160; idx += 256) {
        const int co = idx / 160, r = idx - co * 160;
        pool[co * 165 + r] = conv1_w[idx];
    }
    if (t < 32) pool[5280 + t] = conv1_b[t];
    __syncthreads();

    if (t < 160) {
        const int co = t & 31, q = t >> 5;
        float a0 = pool[5280 + co];
        float a1 = a0;
        const float* wrow = pool + co * 165;
        for (int ci = 0; ci < 32; ci++) {
            #pragma unroll
            for (int k = 0; k < 5; k++) {
                const float w = wrow[ci * 5 + k];
                const int p0 = 2 * q + k - 2;
                const int p1 = p0 + 1;
                if (p0 >= 0 && p0 < 10) a0 += w * pooled[p0 * 33 + ci];
                if (p1 >= 0 && p1 < 10) a1 += w * pooled[p1 * 33 + ci];
            }
        }
        ybuf[co * 5 + q] = fmaxf(fmaxf(a0, 0.f), fmaxf(a1, 0.f));
    }
    __syncthreads();

    // ------------------------------------------------------------------
    // Conv2 (32->16, k=5, pad=2) + ReLU, mean, scorer MLP
    // ------------------------------------------------------------------
    for (int idx = t; idx < 16 * 160; idx += 256) {
        const int co = idx / 160, r = idx - co * 160;
        pool[co * 165 + r] = conv2_w[idx];
    }
    if (t < 16)                pool[2640 + t] = conv2_b[t];
    for (int idx = t; idx < 256; idx += 256) pool[2660 + idx] = sc_w1[idx];
    if (t < 16)                pool[2920 + t] = sc_b1[t];
    if (t >= 16 && t < 32)     pool[2940 + (t - 16)] = sc_w2[t - 16];
    if (t == 32)               pool[2960] = sc_b2[0];
    __syncthreads();

    if (t < 80) {
        const int co = t & 15, p = t >> 4;
        float a = pool[2640 + co];
        const float* wrow = pool + co * 165;
        for (int ci = 0; ci < 32; ci++) {
            #pragma unroll
            for (int k = 0; k < 5; k++) {
                const int q = p + k - 2;
                if (q >= 0 && q < 5) a += wrow[ci * 5 + k] * ybuf[ci * 5 + q];
            }
        }
        c2buf[co * 5 + p] = fmaxf(a, 0.f);
    }
    __syncthreads();

    if (t < 16) {
        feat[t] = 0.2f * (c2buf[t * 5 + 0] + c2buf[t * 5 + 1] + c2buf[t * 5 + 2] +
                          c2buf[t * 5 + 3] + c2buf[t * 5 + 4]);
    }
    __syncthreads();

    if (t < 16) {
        float a = pool[2920 + t];
        #pragma unroll
        for (int i = 0; i < 16; i++) a += feat[i] * pool[2660 + i * 16 + t];
        hidbuf[t] = fmaxf(a, 0.f);
    }
    __syncthreads();

    if (t == 0) {
        float s = pool[2960];
        #pragma unroll
        for (int j = 0; j < 16; j++) s += hidbuf[j] * pool[2940 + j];
        out[g] = s;
    }
}

extern "C" void kernel_launch(void* const* d_in, const int* in_sizes, int n_in,
                              void* d_out, int out_size)
{
    const int B = in_sizes[0] / 64;
    seal_kernel<<<B, 256>>>(
        (const int*)d_in[0], (const int*)d_in[1], (const int*)d_in[2],
        (const float*)d_in[3],
        (const float*)d_in[4],  (const float*)d_in[5],
        (const float*)d_in[6],  (const float*)d_in[7],
        (const float*)d_in[8],  (const float*)d_in[9],
        (const float*)d_in[10], (const float*)d_in[11],
        (const float*)d_in[12], (const float*)d_in[13],
        (const float*)d_in[14], (const float*)d_in[15],
        (const float*)d_in[16], (const float*)d_in[17],
        (const float*)d_in[18], (const float*)d_in[19],
        (const float*)d_in[20], (const float*)d_in[21],
        (const float*)d_in[22], (const float*)d_in[23],
        (float*)d_out);
}